// round 1
// baseline (speedup 1.0000x reference)
#include <cuda_runtime.h>
#include <cstdint>

#define NROWS 262144
#define INF   64
#define HID   256
#define EMB   128
#define OUTD  64
#define NSEG  1024

// ---------------- scratch (device globals: no allocation allowed) ----------------
__device__ float g_h1[(size_t)NROWS * HID];   // 256 MB  (also reused for z1)
__device__ float g_h2[(size_t)NROWS * HID];   // 256 MB  (also reused for z2)
__device__ float g_h [(size_t)NROWS * EMB];   // 128 MB  (embedding h)
__device__ float g_sums[NSEG * EMB];
__device__ float g_cnts[NSEG];
__device__ float g_mp  [NSEG * HID];          // means @ A1[128:,:] + c1
__device__ int   g_ids [NROWS];
__device__ int   g_maxa;

// ---------------- small kernels ----------------
__global__ void k_reset() {
    int i = blockIdx.x * blockDim.x + threadIdx.x;
    if (i < NSEG * EMB) g_sums[i] = 0.0f;
    if (i < NSEG)       g_cnts[i] = 0.0f;
    if (i == 0)         g_maxa = 0;
}

__global__ void k_max(const int* __restrict__ aisle) {
    int i = blockIdx.x * blockDim.x + threadIdx.x;
    int v = (i < NROWS) ? aisle[i] : 0;
    #pragma unroll
    for (int o = 16; o > 0; o >>= 1) v = max(v, __shfl_xor_sync(0xffffffffu, v, o));
    if ((threadIdx.x & 31) == 0) atomicMax(&g_maxa, v);
}

__global__ void k_ids(const int* __restrict__ aisle, const int* __restrict__ batch) {
    int i = blockIdx.x * blockDim.x + threadIdx.x;
    if (i < NROWS) {
        int id = aisle[i] + batch[i] * (g_maxa + 1);
        g_ids[i] = id;
        atomicAdd(&g_cnts[id], 1.0f);
    }
}

// scatter h into segment sums (direct global atomics; optimize later)
__global__ void k_scatter() {
    int i = blockIdx.x * blockDim.x + threadIdx.x;   // over NROWS*EMB
    int row = i >> 7;
    int d   = i & (EMB - 1);
    atomicAdd(&g_sums[g_ids[row] * EMB + d], g_h[i]);
}

// per-segment: means = sums/max(cnt,1); mp[s][j] = sum_d means[d]*A1[(EMB+d)*HID+j] + c1[j]
__global__ void k_meanspart(const float* __restrict__ A1, const float* __restrict__ c1) {
    int s = blockIdx.x;
    int j = threadIdx.x;          // 0..HID-1 (256 threads)
    __shared__ float m[EMB];
    float inv = 1.0f / fmaxf(g_cnts[s], 1.0f);
    if (j < EMB) m[j] = g_sums[s * EMB + j] * inv;
    __syncthreads();
    float acc = c1[j];
    #pragma unroll 8
    for (int d = 0; d < EMB; d++)
        acc += m[d] * A1[(size_t)(EMB + d) * HID + j];
    g_mp[s * HID + j] = acc;
}

// ---------------- tiled fp32 GEMM: C[N,NC] = act(A[N,K] @ W[K,NC] + bias) ----------------
// BM=BN=64, BK=16, 256 threads, 4x4 microtile per thread.
// GATHER=false: bias is a length-NC vector. GATHER=true: bias row = bias + ids[row]*NC.
template<int K, int NC, bool LRELU, bool GATHER>
__global__ __launch_bounds__(256) void k_gemm(const float* __restrict__ A,
                                              const float* __restrict__ W,
                                              const float* __restrict__ bias,
                                              const int*   __restrict__ ids,
                                              float*       __restrict__ C)
{
    constexpr int BK = 16;
    __shared__ float As[BK][64];   // transposed A tile
    __shared__ float Ws[BK][64];

    const int tid  = threadIdx.x;
    const int ty   = tid >> 4;         // 0..15
    const int tx   = tid & 15;         // 0..15
    const int row0 = blockIdx.y * 64;
    const int col0 = blockIdx.x * 64;

    float acc[4][4] = {};

    const int arow = tid >> 2;          // 0..63
    const int akq  = (tid & 3) << 2;    // 0,4,8,12
    const int wk   = tid >> 4;          // 0..15
    const int wcq  = (tid & 15) << 2;   // 0..60

    const float* Ag = A + (size_t)(row0 + arow) * K + akq;
    const float* Wg = W + (size_t)wk * NC + col0 + wcq;

    for (int k0 = 0; k0 < K; k0 += BK) {
        float4 av = *(const float4*)(Ag + k0);
        As[akq + 0][arow] = av.x;
        As[akq + 1][arow] = av.y;
        As[akq + 2][arow] = av.z;
        As[akq + 3][arow] = av.w;
        *(float4*)&Ws[wk][wcq] = *(const float4*)(Wg + (size_t)k0 * NC);
        __syncthreads();

        #pragma unroll
        for (int k = 0; k < BK; k++) {
            float4 a = *(const float4*)&As[k][ty << 2];
            float4 w = *(const float4*)&Ws[k][tx << 2];
            acc[0][0] += a.x * w.x; acc[0][1] += a.x * w.y; acc[0][2] += a.x * w.z; acc[0][3] += a.x * w.w;
            acc[1][0] += a.y * w.x; acc[1][1] += a.y * w.y; acc[1][2] += a.y * w.z; acc[1][3] += a.y * w.w;
            acc[2][0] += a.z * w.x; acc[2][1] += a.z * w.y; acc[2][2] += a.z * w.z; acc[2][3] += a.z * w.w;
            acc[3][0] += a.w * w.x; acc[3][1] += a.w * w.y; acc[3][2] += a.w * w.z; acc[3][3] += a.w * w.w;
        }
        __syncthreads();
    }

    #pragma unroll
    for (int i = 0; i < 4; i++) {
        int row = row0 + (ty << 2) + i;
        const float* brow = GATHER ? (bias + (size_t)ids[row] * NC) : bias;
        float4 o;
        float v0 = acc[i][0] + brow[col0 + (tx << 2) + 0];
        float v1 = acc[i][1] + brow[col0 + (tx << 2) + 1];
        float v2 = acc[i][2] + brow[col0 + (tx << 2) + 2];
        float v3 = acc[i][3] + brow[col0 + (tx << 2) + 3];
        if (LRELU) {
            v0 = v0 > 0.0f ? v0 : 0.01f * v0;
            v1 = v1 > 0.0f ? v1 : 0.01f * v1;
            v2 = v2 > 0.0f ? v2 : 0.01f * v2;
            v3 = v3 > 0.0f ? v3 : 0.01f * v3;
        }
        o.x = v0; o.y = v1; o.z = v2; o.w = v3;
        *(float4*)&C[(size_t)row * NC + col0 + (tx << 2)] = o;
    }
}

// ---------------- launch ----------------
extern "C" void kernel_launch(void* const* d_in, const int* in_sizes, int n_in,
                              void* d_out, int out_size)
{
    const float* x     = (const float*)d_in[0];
    const int*   aisle = (const int*)  d_in[1];
    const int*   batch = (const int*)  d_in[2];
    const float* W1 = (const float*)d_in[3];  const float* b1 = (const float*)d_in[4];
    const float* W2 = (const float*)d_in[5];  const float* b2 = (const float*)d_in[6];
    const float* W3 = (const float*)d_in[7];  const float* b3 = (const float*)d_in[8];
    const float* A1 = (const float*)d_in[9];  const float* c1 = (const float*)d_in[10];
    const float* A2 = (const float*)d_in[11]; const float* c2 = (const float*)d_in[12];
    const float* A3 = (const float*)d_in[13]; const float* c3 = (const float*)d_in[14];
    float* out = (float*)d_out;

    float *h1, *h2, *h, *mp; int* ids;
    cudaGetSymbolAddress((void**)&h1,  g_h1);
    cudaGetSymbolAddress((void**)&h2,  g_h2);
    cudaGetSymbolAddress((void**)&h,   g_h);
    cudaGetSymbolAddress((void**)&mp,  g_mp);
    cudaGetSymbolAddress((void**)&ids, g_ids);

    k_reset<<<(NSEG * EMB + 255) / 256, 256>>>();
    k_max  <<<NROWS / 256, 256>>>(aisle);
    k_ids  <<<NROWS / 256, 256>>>(aisle, batch);

    // layer 1: h1 = lrelu(x @ W1 + b1)           [N,64]  -> [N,256]
    k_gemm<INF, HID, true,  false><<<dim3(HID / 64, NROWS / 64), 256>>>(x,  W1, b1, nullptr, h1);
    // layer 2: h2 = lrelu(h1 @ W2 + b2)          [N,256] -> [N,256]
    k_gemm<HID, HID, true,  false><<<dim3(HID / 64, NROWS / 64), 256>>>(h1, W2, b2, nullptr, h2);
    // layer 3: h = h2 @ W3 + b3                  [N,256] -> [N,128]
    k_gemm<HID, EMB, false, false><<<dim3(EMB / 64, NROWS / 64), 256>>>(h2, W3, b3, nullptr, h);

    // segment sums + per-segment bias part of layer 4
    k_scatter<<<(size_t)NROWS * EMB / 256, 256>>>();
    k_meanspart<<<NSEG, HID>>>(A1, c1);

    // layer 4: z1 = lrelu(h @ A1[:128,:] + mp[ids])   (gathered per-row bias)
    k_gemm<EMB, HID, true,  true ><<<dim3(HID / 64, NROWS / 64), 256>>>(h,  A1, mp, ids, h1);
    // layer 5: z2 = lrelu(z1 @ A2 + c2)
    k_gemm<HID, HID, true,  false><<<dim3(HID / 64, NROWS / 64), 256>>>(h1, A2, c2, nullptr, h2);
    // layer 6: out = z2 @ A3 + c3                [N,256] -> [N,64]
    k_gemm<HID, OUTD, false, false><<<dim3(OUTD / 64, NROWS / 64), 256>>>(h2, A3, c3, nullptr, out);
}

// round 3
// speedup vs baseline: 1.0653x; 1.0653x over previous
#include <cuda_runtime.h>
#include <cuda_bf16.h>
#include <mma.h>
#include <cstdint>

using namespace nvcuda;

#define NROWS 262144
#define INF   64
#define HID   256
#define EMB   128
#define OUTD  64
#define NSEG  1024

// ======================= scratch =======================
__device__ float g_t1[(size_t)NROWS * HID];
__device__ float g_t2[(size_t)NROWS * HID];
__device__ float g_h [(size_t)NROWS * EMB];
__device__ float g_sums[NSEG * EMB];
__device__ float g_cnts[NSEG];
__device__ float g_mp  [NSEG * HID];
__device__ int   g_ids [NROWS];
__device__ int   g_maxa;

// ======================= small kernels =======================
__global__ void k_reset() {
    int i = blockIdx.x * blockDim.x + threadIdx.x;
    if (i < NSEG * EMB) g_sums[i] = 0.0f;
    if (i < NSEG)       g_cnts[i] = 0.0f;
    if (i == 0)         g_maxa = 0;
}
__global__ void k_max(const int* __restrict__ aisle) {
    int i = blockIdx.x * blockDim.x + threadIdx.x;
    int v = (i < NROWS) ? aisle[i] : 0;
    #pragma unroll
    for (int o = 16; o > 0; o >>= 1) v = max(v, __shfl_xor_sync(0xffffffffu, v, o));
    if ((threadIdx.x & 31) == 0) atomicMax(&g_maxa, v);
}
__global__ void k_ids(const int* __restrict__ aisle, const int* __restrict__ batch) {
    int i = blockIdx.x * blockDim.x + threadIdx.x;
    if (i < NROWS) {
        int id = aisle[i] + batch[i] * (g_maxa + 1);
        g_ids[i] = id;
        atomicAdd(&g_cnts[id], 1.0f);
    }
}
__global__ void k_scatter(const float* __restrict__ h) {
    int i = blockIdx.x * blockDim.x + threadIdx.x;   // over NROWS*EMB
    int row = i >> 7;
    int d   = i & (EMB - 1);
    atomicAdd(&g_sums[g_ids[row] * EMB + d], h[i]);
}
__global__ void k_meanspart(const float* __restrict__ A1, const float* __restrict__ c1) {
    int s = blockIdx.x;
    int j = threadIdx.x;
    __shared__ float m[EMB];
    float inv = 1.0f / fmaxf(g_cnts[s], 1.0f);
    if (j < EMB) m[j] = g_sums[s * EMB + j] * inv;
    __syncthreads();
    float acc = c1[j];
    #pragma unroll 8
    for (int d = 0; d < EMB; d++)
        acc += m[d] * A1[(size_t)(EMB + d) * HID + j];
    g_mp[s * HID + j] = acc;
}

// ======================= wmma (HMMA) GEMM =======================
// C[128, NC] = act(A[128,K] @ W[K,NC] + bias), fp32 in gmem everywhere.
// bf16 hi/lo split (3 products) happens on the fly while filling smem.
__device__ __forceinline__ void split2(float v0, float v1,
                                       __nv_bfloat162& h2, __nv_bfloat162& l2) {
    __nv_bfloat16 h0 = __float2bfloat16(v0);
    __nv_bfloat16 h1 = __float2bfloat16(v1);
    __nv_bfloat16 l0 = __float2bfloat16(v0 - __bfloat162float(h0));
    __nv_bfloat16 l1 = __float2bfloat16(v1 - __bfloat162float(h1));
    h2 = __nv_bfloat162(h0, h1);
    l2 = __nv_bfloat162(l0, l1);
}

template<int K, int NC, bool LRELU, bool GATHER>
__global__ __launch_bounds__(256) void k_tcw(
    const float* __restrict__ A, const float* __restrict__ W,
    const float* __restrict__ bias, const int* __restrict__ ids,
    float* __restrict__ C)
{
    constexpr int SA = K + 8;     // padded A stride (elements)
    constexpr int SB = 72;        // padded W stride (64 + 8)
    constexpr int APLANE = 128 * SA;   // elements per A plane
    constexpr int WPLANE = K * SB;     // elements per W plane

    extern __shared__ char smem[];
    __nv_bfloat16* Ah = (__nv_bfloat16*)smem;
    __nv_bfloat16* Al = Ah + APLANE;
    __nv_bfloat16* Wh = Al + APLANE;
    __nv_bfloat16* Wl = Wh + WPLANE;
    float* stage = (float*)(Al + APLANE);   // aliases the W region (dead during epilogue)

    const int tid  = threadIdx.x;
    const int wid  = tid >> 5;
    const int lane = tid & 31;
    const int row0 = blockIdx.x * 128;
    const int wm   = wid & 3;          // 4 warps over M (32 rows each)
    const int wn   = wid >> 2;         // 2 warps over N (32 cols each)

    // ---- stage A block [128, K] fp32 -> hi/lo bf16 smem planes ----
    for (int i = tid; i < 128 * (K / 4); i += 256) {
        int r  = i / (K / 4);
        int c4 = (i % (K / 4)) * 4;
        float4 v = *(const float4*)(A + (size_t)(row0 + r) * K + c4);
        __nv_bfloat162 h01, l01, h23, l23;
        split2(v.x, v.y, h01, l01);
        split2(v.z, v.w, h23, l23);
        int o = r * SA + c4;
        *(__nv_bfloat162*)(Ah + o)     = h01;
        *(__nv_bfloat162*)(Ah + o + 2) = h23;
        *(__nv_bfloat162*)(Al + o)     = l01;
        *(__nv_bfloat162*)(Al + o + 2) = l23;
    }

    for (int n0 = 0; n0 < NC; n0 += 64) {
        __syncthreads();   // A staged (1st iter) / previous stage reads done
        // ---- stage W tile [K, 64] fp32 -> hi/lo bf16 smem ----
        for (int i = tid; i < K * 16; i += 256) {
            int k  = i / 16;
            int c4 = (i % 16) * 4;
            float4 v = *(const float4*)(W + (size_t)k * NC + n0 + c4);
            __nv_bfloat162 h01, l01, h23, l23;
            split2(v.x, v.y, h01, l01);
            split2(v.z, v.w, h23, l23);
            int o = k * SB + c4;
            *(__nv_bfloat162*)(Wh + o)     = h01;
            *(__nv_bfloat162*)(Wh + o + 2) = h23;
            *(__nv_bfloat162*)(Wl + o)     = l01;
            *(__nv_bfloat162*)(Wl + o + 2) = l23;
        }
        __syncthreads();

        wmma::fragment<wmma::accumulator, 16, 16, 16, float> acc[2][2];
        #pragma unroll
        for (int mi = 0; mi < 2; mi++)
            #pragma unroll
            for (int ni = 0; ni < 2; ni++)
                wmma::fill_fragment(acc[mi][ni], 0.0f);

        #pragma unroll
        for (int k0 = 0; k0 < K; k0 += 16) {
            wmma::fragment<wmma::matrix_a, 16, 16, 16, __nv_bfloat16, wmma::row_major> ah[2], al[2];
            wmma::fragment<wmma::matrix_b, 16, 16, 16, __nv_bfloat16, wmma::row_major> bh[2], bl[2];
            #pragma unroll
            for (int mi = 0; mi < 2; mi++) {
                int ro = (wm * 32 + mi * 16) * SA + k0;
                wmma::load_matrix_sync(ah[mi], Ah + ro, SA);
                wmma::load_matrix_sync(al[mi], Al + ro, SA);
            }
            #pragma unroll
            for (int ni = 0; ni < 2; ni++) {
                int co = k0 * SB + wn * 32 + ni * 16;
                wmma::load_matrix_sync(bh[ni], Wh + co, SB);
                wmma::load_matrix_sync(bl[ni], Wl + co, SB);
            }
            #pragma unroll
            for (int mi = 0; mi < 2; mi++)
                #pragma unroll
                for (int ni = 0; ni < 2; ni++) {
                    wmma::mma_sync(acc[mi][ni], ah[mi], bh[ni], acc[mi][ni]);
                    wmma::mma_sync(acc[mi][ni], ah[mi], bl[ni], acc[mi][ni]);
                    wmma::mma_sync(acc[mi][ni], al[mi], bh[ni], acc[mi][ni]);
                }
        }

        __syncthreads();   // all warps done reading W before stage overwrites it
        float* st = stage + wid * 1024;   // 32x32 per-warp staging tile
        #pragma unroll
        for (int mi = 0; mi < 2; mi++)
            #pragma unroll
            for (int ni = 0; ni < 2; ni++)
                wmma::store_matrix_sync(st + mi * 16 * 32 + ni * 16, acc[mi][ni], 32,
                                        wmma::mem_row_major);
        __syncwarp();

        // epilogue: bias (+gathered segment bias), leaky-relu, coalesced fp32 stores
        #pragma unroll 4
        for (int r = 0; r < 32; r++) {
            int row = row0 + wm * 32 + r;
            int col = n0 + wn * 32 + lane;
            const float* brow = GATHER ? (bias + (size_t)ids[row] * NC) : bias;
            float v = st[r * 32 + lane] + brow[col];
            if (LRELU) v = v > 0.0f ? v : 0.01f * v;
            C[(size_t)row * NC + col] = v;
        }
    }
}

// smem bytes: A planes + max(W planes, stage)
static constexpr int smem_for(int K) {
    int a = 4 * 128 * (K + 8);
    int w = 4 * K * 72;
    int st = 8 * 32 * 32 * 4;
    return a + (w > st ? w : st);
}

// ======================= launch =======================
extern "C" void kernel_launch(void* const* d_in, const int* in_sizes, int n_in,
                              void* d_out, int out_size)
{
    const float* x     = (const float*)d_in[0];
    const int*   aisle = (const int*)  d_in[1];
    const int*   batch = (const int*)  d_in[2];
    const float* W1 = (const float*)d_in[3];  const float* b1 = (const float*)d_in[4];
    const float* W2 = (const float*)d_in[5];  const float* b2 = (const float*)d_in[6];
    const float* W3 = (const float*)d_in[7];  const float* b3 = (const float*)d_in[8];
    const float* A1 = (const float*)d_in[9];  const float* c1 = (const float*)d_in[10];
    const float* A2 = (const float*)d_in[11]; const float* c2 = (const float*)d_in[12];
    const float* A3 = (const float*)d_in[13]; const float* c3 = (const float*)d_in[14];
    float* out = (float*)d_out;

    float *t1, *t2, *h, *mp; int* ids;
    cudaGetSymbolAddress((void**)&t1,  g_t1);
    cudaGetSymbolAddress((void**)&t2,  g_t2);
    cudaGetSymbolAddress((void**)&h,   g_h);
    cudaGetSymbolAddress((void**)&mp,  g_mp);
    cudaGetSymbolAddress((void**)&ids, g_ids);

    cudaFuncSetAttribute(k_tcw<INF, HID, true,  false>, cudaFuncAttributeMaxDynamicSharedMemorySize, smem_for(INF));
    cudaFuncSetAttribute(k_tcw<HID, HID, true,  false>, cudaFuncAttributeMaxDynamicSharedMemorySize, smem_for(HID));
    cudaFuncSetAttribute(k_tcw<HID, EMB, false, false>, cudaFuncAttributeMaxDynamicSharedMemorySize, smem_for(HID));
    cudaFuncSetAttribute(k_tcw<EMB, HID, true,  true >, cudaFuncAttributeMaxDynamicSharedMemorySize, smem_for(EMB));
    cudaFuncSetAttribute(k_tcw<HID, OUTD, false, false>, cudaFuncAttributeMaxDynamicSharedMemorySize, smem_for(HID));

    k_reset<<<(NSEG * EMB + 255) / 256, 256>>>();
    k_max  <<<NROWS / 256, 256>>>(aisle);
    k_ids  <<<NROWS / 256, 256>>>(aisle, batch);

    const int GB = NROWS / 128;  // 2048 row-blocks
    // layer 1: t1 = lrelu(x @ W1 + b1)            [N,64]  -> [N,256]
    k_tcw<INF, HID, true,  false><<<GB, 256, smem_for(INF)>>>(x,  W1, b1, nullptr, t1);
    // layer 2: t2 = lrelu(t1 @ W2 + b2)           [N,256] -> [N,256]
    k_tcw<HID, HID, true,  false><<<GB, 256, smem_for(HID)>>>(t1, W2, b2, nullptr, t2);
    // layer 3: h = t2 @ W3 + b3                   [N,256] -> [N,128]
    k_tcw<HID, EMB, false, false><<<GB, 256, smem_for(HID)>>>(t2, W3, b3, nullptr, h);

    // segment means + per-segment partial of layer 4
    k_scatter<<<(size_t)NROWS * EMB / 256, 256>>>(h);
    k_meanspart<<<NSEG, HID>>>(A1, c1);

    // layer 4: t1 = lrelu(h @ A1[:128,:] + mp[ids])
    k_tcw<EMB, HID, true,  true ><<<GB, 256, smem_for(EMB)>>>(h,  A1, mp, ids, t1);
    // layer 5: t2 = lrelu(t1 @ A2 + c2)
    k_tcw<HID, HID, true,  false><<<GB, 256, smem_for(HID)>>>(t1, A2, c2, nullptr, t2);
    // layer 6: out = t2 @ A3 + c3                 [N,256] -> [N,64]
    k_tcw<HID, OUTD, false, false><<<GB, 256, smem_for(HID)>>>(t2, A3, c3, nullptr, out);
}